// round 3
// baseline (speedup 1.0000x reference)
#include <cuda_runtime.h>
#include <math.h>
#include <stdint.h>

// ---------------- problem constants ----------------
#define Bx 16
#define Sx 384
#define Hx 768
#define DKx 64
#define ESSx 6
#define WHOLEx 8
#define HEADERx 9
#define IGx 672
#define IPx 960
#define H2x 1536
#define Px 73920              // S*(S+1)/2
#define Mx (Bx*Sx)            // 6144

// ---------------- scratch (device globals; no allocations) ----------------
__device__ float g_cos[Sx*32];
__device__ float g_sin[Sx*32];
__device__ float g_lin[Mx*576];
__device__ float g_hid[Mx*IPx];
__device__ float g_tsq[Bx*Sx*DKx];
__device__ float g_tsk[Bx*Sx*DKx];
__device__ float g_qg [Bx*HEADERx*Sx*DKx];
__device__ float g_kg [Bx*HEADERx*Sx*DKx];
__device__ float g_scg[(size_t)Bx*HEADERx*Sx*Sx];
__device__ float g_adj[(size_t)Bx*HEADERx*Sx*Sx];
__device__ float g_hr [(size_t)HEADERx*Bx*Sx*Hx];
__device__ float g_feat[Mx*Hx];
__device__ float g_agg [Mx*Hx];
__device__ float g_inp [Mx*H2x];
__device__ float g_tq[Bx*Sx*DKx];
__device__ float g_tk[Bx*Sx*DKx];
__device__ float g_qp[Bx*ESSx*Sx*DKx];
__device__ float g_kp[Bx*ESSx*Sx*DKx];
__device__ float g_stg[(size_t)Bx*Sx*Sx];
__device__ float g_stp[(size_t)Bx*Sx*Sx];
__device__ float g_sp [(size_t)Bx*ESSx*Sx*Sx];

// ---------------- rope tables ----------------
__global__ void k_init_rope() {
    int idx = blockIdx.x * blockDim.x + threadIdx.x;
    if (idx >= Sx * 32) return;
    int p = idx / 32, i = idx & 31;
    double theta = (double)p * pow(10000.0, -(double)i / 32.0);
    g_cos[idx] = (float)cos(theta);
    g_sin[idx] = (float)sin(theta);
}

// ---------------- tf32 helpers ----------------
__device__ __forceinline__ uint32_t f2tf(float x) {
    uint32_t r;
    asm("cvt.rna.tf32.f32 %0, %1;" : "=r"(r) : "f"(x));
    return r;
}

__device__ __forceinline__ void mma_tf32(float* d, const uint32_t* a, const uint32_t* b) {
    asm volatile(
        "mma.sync.aligned.m16n8k8.row.col.f32.tf32.tf32.f32 "
        "{%0,%1,%2,%3},{%4,%5,%6,%7},{%8,%9},{%0,%1,%2,%3};"
        : "+f"(d[0]), "+f"(d[1]), "+f"(d[2]), "+f"(d[3])
        : "r"(a[0]), "r"(a[1]), "r"(a[2]), "r"(a[3]), "r"(b[0]), "r"(b[1]));
}

#define SWX(k) (((((k) >> 2) & 3)) << 3)

// ---------------- 3xTF32 tensor-core GEMM:  C[z] = act( A[z] @ W[z]^T * scale + bias ) ----------------
// BM=BN=128, BK=16, 512 threads (16 warps 4x4), warp tile 32x32.
// M % 128 == 0, K % 16 == 0, N arbitrary (even), guarded.
__global__ void __launch_bounds__(512) k_mma(
    const float* __restrict__ A, long astr,
    const float* __restrict__ W, long wstr,
    const float* __restrict__ bias,
    float* __restrict__ C, long cstr,
    int M, int N, int K, int relu, float scale)
{
    __shared__ uint32_t Ah[16][136], Al[16][136], Bh[16][136], Bl[16][136];

    const float* Az = A + (long)blockIdx.z * astr;
    const float* Wz = W + (long)blockIdx.z * wstr;
    float* Cz = C + (long)blockIdx.z * cstr;

    int tid = threadIdx.x, lane = tid & 31;
    int g = lane >> 2, tg = lane & 3;
    int wid = tid >> 5, wm = wid >> 2, wn = wid & 3;
    int row0 = blockIdx.y * 128, col0 = blockIdx.x * 128;
    int lr = tid >> 2, lk = (tid & 3) * 4;

    float acc[2][4][4] = {};

    const float* ap = Az + (long)(row0 + lr) * K + lk;
    bool wok = (col0 + lr) < N;
    const float* wp = Wz + (long)(wok ? (col0 + lr) : 0) * K + lk;

    for (int k0 = 0; k0 < K; k0 += 16) {
        float4 av = *(const float4*)ap; ap += 16;
        float4 wv = wok ? *(const float4*)wp : make_float4(0.f,0.f,0.f,0.f); wp += 16;
        float va[4] = {av.x, av.y, av.z, av.w};
        float vw[4] = {wv.x, wv.y, wv.z, wv.w};
#pragma unroll
        for (int j = 0; j < 4; ++j) {
            int kk = lk + j;
            int c = lr ^ SWX(kk);
            uint32_t h = f2tf(va[j]);
            Ah[kk][c] = h;
            Al[kk][c] = f2tf(va[j] - __uint_as_float(h));
            uint32_t hw = f2tf(vw[j]);
            Bh[kk][c] = hw;
            Bl[kk][c] = f2tf(vw[j] - __uint_as_float(hw));
        }
        __syncthreads();

#pragma unroll
        for (int ks = 0; ks < 16; ks += 8) {
            int k1 = ks + tg, k2 = ks + tg + 4;
            int x1 = SWX(k1), x2 = SWX(k2);
            uint32_t ah[2][4], al[2][4], bh[4][2], bl[4][2];
#pragma unroll
            for (int mt = 0; mt < 2; ++mt) {
                int r = wm * 32 + mt * 16 + g;
                ah[mt][0] = Ah[k1][r ^ x1];       ah[mt][1] = Ah[k1][(r + 8) ^ x1];
                ah[mt][2] = Ah[k2][r ^ x2];       ah[mt][3] = Ah[k2][(r + 8) ^ x2];
                al[mt][0] = Al[k1][r ^ x1];       al[mt][1] = Al[k1][(r + 8) ^ x1];
                al[mt][2] = Al[k2][r ^ x2];       al[mt][3] = Al[k2][(r + 8) ^ x2];
            }
#pragma unroll
            for (int nt = 0; nt < 4; ++nt) {
                int c = wn * 32 + nt * 8 + g;
                bh[nt][0] = Bh[k1][c ^ x1];       bh[nt][1] = Bh[k2][c ^ x2];
                bl[nt][0] = Bl[k1][c ^ x1];       bl[nt][1] = Bl[k2][c ^ x2];
            }
#pragma unroll
            for (int mt = 0; mt < 2; ++mt)
#pragma unroll
                for (int nt = 0; nt < 4; ++nt) {
                    mma_tf32(acc[mt][nt], al[mt], bh[nt]);
                    mma_tf32(acc[mt][nt], ah[mt], bl[nt]);
                    mma_tf32(acc[mt][nt], ah[mt], bh[nt]);
                }
        }
        __syncthreads();
    }

#pragma unroll
    for (int mt = 0; mt < 2; ++mt) {
        int r = row0 + wm * 32 + mt * 16 + g;
#pragma unroll
        for (int nt = 0; nt < 4; ++nt) {
            int c = col0 + wn * 32 + nt * 8 + 2 * tg;
            if (c < N) {
                float b0v = bias ? bias[c] : 0.f;
                float b1v = bias ? bias[c + 1] : 0.f;
                float2 v0 = make_float2(acc[mt][nt][0] * scale + b0v,
                                        acc[mt][nt][1] * scale + b1v);
                float2 v1 = make_float2(acc[mt][nt][2] * scale + b0v,
                                        acc[mt][nt][3] * scale + b1v);
                if (relu) {
                    v0.x = fmaxf(v0.x, 0.f); v0.y = fmaxf(v0.y, 0.f);
                    v1.x = fmaxf(v1.x, 0.f); v1.y = fmaxf(v1.y, 0.f);
                }
                *(float2*)&Cz[(long)r * N + c] = v0;
                *(float2*)&Cz[(long)(r + 8) * N + c] = v1;
            }
        }
    }
}

// ---------------- 3xTF32 fused RGAT aggregation: out[b] = sum_r relu( adj[b,r] @ hr[r,b] ) ----------------
// BM=128 (s), BN=64 (o), BK=16, 256 threads (8 warps 4x2), warp tile 32x32.
__global__ void __launch_bounds__(256) k_mma_agg(
    const float* __restrict__ adj, const float* __restrict__ hr,
    float* __restrict__ out)
{
    __shared__ uint32_t Ah[16][136], Al[16][136], Bh[16][72], Bl[16][72];

    int b = blockIdx.z;
    int row0 = blockIdx.y * 128, col0 = blockIdx.x * 64;

    int tid = threadIdx.x, lane = tid & 31;
    int g = lane >> 2, tg = lane & 3;
    int wid = tid >> 5, wm = wid >> 1, wn = wid & 1;
    int lr = tid >> 1, lk = (tid & 1) * 8;       // adj tile loader
    int kr = tid >> 4, kc = (tid & 15) * 4;      // hr tile loader

    float sum[2][4][4] = {};

    for (int r = 0; r < HEADERx; ++r) {
        const float* adjbr = adj + ((long)(b * HEADERx + r)) * Sx * Sx;
        const float* hrrb  = hr  + ((long)(r * Bx + b)) * Sx * Hx;
        float acc[2][4][4] = {};

        for (int k0 = 0; k0 < Sx; k0 += 16) {
            const float* ap = adjbr + (long)(row0 + lr) * Sx + k0 + lk;
            float4 a0 = *(const float4*)ap;
            float4 a1 = *(const float4*)(ap + 4);
            float va[8] = {a0.x,a0.y,a0.z,a0.w,a1.x,a1.y,a1.z,a1.w};
#pragma unroll
            for (int j = 0; j < 8; ++j) {
                int kk = lk + j;
                int c = lr ^ SWX(kk);
                uint32_t h = f2tf(va[j]);
                Ah[kk][c] = h;
                Al[kk][c] = f2tf(va[j] - __uint_as_float(h));
            }
            const float* bp = hrrb + (long)(k0 + kr) * Hx + col0 + kc;
            float4 bv = *(const float4*)bp;
            {
                int c = kc ^ SWX(kr);
                float vb[4] = {bv.x, bv.y, bv.z, bv.w};
#pragma unroll
                for (int j = 0; j < 4; ++j) {
                    uint32_t h = f2tf(vb[j]);
                    Bh[kr][c + j] = h;
                    Bl[kr][c + j] = f2tf(vb[j] - __uint_as_float(h));
                }
            }
            __syncthreads();

#pragma unroll
            for (int ks = 0; ks < 16; ks += 8) {
                int k1 = ks + tg, k2 = ks + tg + 4;
                int x1 = SWX(k1), x2 = SWX(k2);
                uint32_t ah[2][4], al[2][4], bh[4][2], bl[4][2];
#pragma unroll
                for (int mt = 0; mt < 2; ++mt) {
                    int rr = wm * 32 + mt * 16 + g;
                    ah[mt][0] = Ah[k1][rr ^ x1];       ah[mt][1] = Ah[k1][(rr + 8) ^ x1];
                    ah[mt][2] = Ah[k2][rr ^ x2];       ah[mt][3] = Ah[k2][(rr + 8) ^ x2];
                    al[mt][0] = Al[k1][rr ^ x1];       al[mt][1] = Al[k1][(rr + 8) ^ x1];
                    al[mt][2] = Al[k2][rr ^ x2];       al[mt][3] = Al[k2][(rr + 8) ^ x2];
                }
#pragma unroll
                for (int nt = 0; nt < 4; ++nt) {
                    int c = wn * 32 + nt * 8 + g;
                    bh[nt][0] = Bh[k1][c ^ x1];        bh[nt][1] = Bh[k2][c ^ x2];
                    bl[nt][0] = Bl[k1][c ^ x1];        bl[nt][1] = Bl[k2][c ^ x2];
                }
#pragma unroll
                for (int mt = 0; mt < 2; ++mt)
#pragma unroll
                    for (int nt = 0; nt < 4; ++nt) {
                        mma_tf32(acc[mt][nt], al[mt], bh[nt]);
                        mma_tf32(acc[mt][nt], ah[mt], bl[nt]);
                        mma_tf32(acc[mt][nt], ah[mt], bh[nt]);
                    }
            }
            __syncthreads();
        }
#pragma unroll
        for (int mt = 0; mt < 2; ++mt)
#pragma unroll
            for (int nt = 0; nt < 4; ++nt)
#pragma unroll
                for (int i = 0; i < 4; ++i)
                    sum[mt][nt][i] += fmaxf(acc[mt][nt][i], 0.f);
    }

#pragma unroll
    for (int mt = 0; mt < 2; ++mt) {
        int s = row0 + wm * 32 + mt * 16 + g;
#pragma unroll
        for (int nt = 0; nt < 4; ++nt) {
            int o = col0 + wn * 32 + nt * 8 + 2 * tg;
            float2 v0 = make_float2(sum[mt][nt][0], sum[mt][nt][1]);
            float2 v1 = make_float2(sum[mt][nt][2], sum[mt][nt][3]);
            *(float2*)&out[((long)b * Sx + s) * Hx + o] = v0;
            *(float2*)&out[((long)b * Sx + s + 8) * Hx + o] = v1;
        }
    }
}

// ---------------- mask + RoPE + head split ----------------
__global__ void k_rope(const float* __restrict__ lin, const float* __restrict__ mask,
                       float* __restrict__ out, int nH)
{
    int bs = blockIdx.x;
    int b = bs / Sx, s = bs % Sx;
    float m = mask[bs];
    int t = threadIdx.x;
    int h = t >> 5, i = t & 31;
    float c  = g_cos[s*32 + i];
    float sn = g_sin[s*32 + i];
    const float* lp = lin + (long)bs * nH * 64 + h * 64 + 2*i;
    float x0 = lp[0] * m, x1 = lp[1] * m;
    float* op = out + (((long)(b*nH + h)) * Sx + s) * 64 + 2*i;
    op[0] = x0 * c - x1 * sn;
    op[1] = x1 * c + x0 * sn;
}

// ---------------- symmetric softmax -> adj ----------------
__global__ void k_adj(const float* __restrict__ score, float* __restrict__ adj)
{
    int blk = blockIdx.x;
    int i = blk % Sx;
    long bh = blk / Sx;
    const float* sc = score + bh * (long)(Sx*Sx);
    float* out = adj + bh * (long)(Sx*Sx) + (long)i * Sx;
    int t = threadIdx.x;
    float v[3];
#pragma unroll
    for (int u = 0; u < 3; ++u) {
        int j = t + u * 128;
        v[u] = (j >= i) ? sc[(long)i*Sx + j] : sc[(long)j*Sx + i];
    }
    __shared__ float red[128];
    float m = fmaxf(v[0], fmaxf(v[1], v[2]));
    red[t] = m; __syncthreads();
#pragma unroll
    for (int st = 64; st > 0; st >>= 1) {
        if (t < st) red[t] = fmaxf(red[t], red[t + st]);
        __syncthreads();
    }
    m = red[0]; __syncthreads();
    float e0 = expf(v[0]-m), e1 = expf(v[1]-m), e2 = expf(v[2]-m);
    red[t] = e0 + e1 + e2; __syncthreads();
#pragma unroll
    for (int st = 64; st > 0; st >>= 1) {
        if (t < st) red[t] += red[t + st];
        __syncthreads();
    }
    float is = 1.f / red[0];
    out[t      ] = (v[0] != 0.f) ? e0 * is : 0.f;
    out[t + 128] = (v[1] != 0.f) ? e1 * is : 0.f;
    out[t + 256] = (v[2] != 0.f) ? e2 * is : 0.f;
}

// ---------------- feat = layernorm( relu(agg)/9 ) ----------------
__global__ void k_ln(const float* __restrict__ a, float* __restrict__ o)
{
    long bs = blockIdx.x;
    const float* x = a + bs * Hx;
    float* y = o + bs * Hx;
    int t = threadIdx.x;
    float v[3];
    float s = 0.f;
#pragma unroll
    for (int u = 0; u < 3; ++u) {
        v[u] = fmaxf(x[t + u*256], 0.f) * (1.f/9.f);
        s += v[u];
    }
    __shared__ float red[256];
    red[t] = s; __syncthreads();
#pragma unroll
    for (int st = 128; st > 0; st >>= 1) {
        if (t < st) red[t] += red[t + st];
        __syncthreads();
    }
    float mean = red[0] * (1.f/768.f); __syncthreads();
    float s2 = 0.f;
#pragma unroll
    for (int u = 0; u < 3; ++u) { float d = v[u] - mean; s2 += d*d; }
    red[t] = s2; __syncthreads();
#pragma unroll
    for (int st = 128; st > 0; st >>= 1) {
        if (t < st) red[t] += red[t + st];
        __syncthreads();
    }
    float var = red[0] * (1.f/768.f);
    float rr = rsqrtf(var + 1e-5f);
#pragma unroll
    for (int u = 0; u < 3; ++u) y[t + u*256] = (v[u] - mean) * rr;
}

// ---------------- inp = concat(x, feat) ----------------
__global__ void k_concat(const float* __restrict__ x, const float* __restrict__ feat,
                         float* __restrict__ inp)
{
    long idx = (long)blockIdx.x * blockDim.x + threadIdx.x;
    if (idx >= (long)Mx * H2x) return;
    long row = idx / H2x;
    int c = (int)(idx % H2x);
    inp[idx] = (c < Hx) ? x[row * Hx + c] : feat[row * Hx + (c - Hx)];
}

// ---------------- gather upper-triangle pairs -> out[B,P,16] ----------------
__global__ void k_pairs(const float* __restrict__ sp, const float* __restrict__ stp,
                        const float* __restrict__ sg, const float* __restrict__ stg,
                        float* __restrict__ out)
{
    int i = blockIdx.x, b = blockIdx.y, j = threadIdx.x;
    if (j < i) return;
    long p  = (long)i * (2*Sx - i + 1) / 2 + (j - i);
    long ss = (long)Sx * Sx;
    long ij = (long)i * Sx + j;
    const float* spb = sp + (long)b * ESSx * ss + ij;
    const float* sgb = sg + (long)b * HEADERx * ss + ij;
    float4 o0, o1, o2, o3;
    o0.x = spb[0];     o0.y = spb[ss];   o0.z = spb[2*ss]; o0.w = spb[3*ss];
    o1.x = spb[4*ss];  o1.y = spb[5*ss];
    o1.z = fmaxf(stp[(long)b*ss + ij], 0.f);
    o1.w = sgb[0];
    o2.x = sgb[ss];    o2.y = sgb[2*ss]; o2.z = sgb[3*ss]; o2.w = sgb[4*ss];
    o3.x = sgb[5*ss];  o3.y = sgb[6*ss]; o3.z = sgb[7*ss];
    o3.w = fmaxf(stg[(long)b*ss + ij], 0.f);
    float4* op = (float4*)(out + ((long)b * Px + p) * 16);
    op[0] = o0; op[1] = o1; op[2] = o2; op[3] = o3;
}

// ---------------- host ----------------
static void launch_gemm(const float* A, long astr, const float* W, long wstr,
                        const float* bias, float* C, long cstr,
                        int M, int N, int K, int relu, float scale, int Z)
{
    dim3 grid((N + 127) / 128, M / 128, Z);
    k_mma<<<grid, 512>>>(A, astr, W, wstr, bias, C, cstr, M, N, K, relu, scale);
}

extern "C" void kernel_launch(void* const* d_in, const int* in_sizes, int n_in,
                              void* d_out, int out_size)
{
    const float* x          = (const float*)d_in[0];
    const float* amask      = (const float*)d_in[1];
    const float* wq4gt_w    = (const float*)d_in[2];
    const float* wq4gt_b    = (const float*)d_in[3];
    const float* wk4gt_w    = (const float*)d_in[4];
    const float* wk4gt_b    = (const float*)d_in[5];
    const float* wq4g_rep_w = (const float*)d_in[6];
    const float* wq4g_rep_b = (const float*)d_in[7];
    const float* wq4g_sc_w  = (const float*)d_in[8];
    const float* wq4g_sc_b  = (const float*)d_in[9];
    const float* wk4g_rep_w = (const float*)d_in[10];
    const float* wk4g_rep_b = (const float*)d_in[11];
    const float* wk4g_sc_w  = (const float*)d_in[12];
    const float* wk4g_sc_b  = (const float*)d_in[13];
    const float* rgat_w     = (const float*)d_in[14];
    const float* wq4t_w     = (const float*)d_in[15];
    const float* wq4t_b     = (const float*)d_in[16];
    const float* wk4t_w     = (const float*)d_in[17];
    const float* wk4t_b     = (const float*)d_in[18];
    const float* wq_rep_w   = (const float*)d_in[19];
    const float* wq_rep_b   = (const float*)d_in[20];
    const float* wq_sc_w    = (const float*)d_in[21];
    const float* wq_sc_b    = (const float*)d_in[22];
    const float* wk_rep_w   = (const float*)d_in[23];
    const float* wk_rep_b   = (const float*)d_in[24];
    const float* wk_sc_w    = (const float*)d_in[25];
    const float* wk_sc_b    = (const float*)d_in[26];
    float* out = (float*)d_out;

    float *lin,*hid,*tsq,*tsk,*qg,*kg,*scg,*adj,*hr,*feat,*agg,*inp,*tq,*tk,*qp,*kp,*stg,*stp,*sp;
    cudaGetSymbolAddress((void**)&lin,  g_lin);
    cudaGetSymbolAddress((void**)&hid,  g_hid);
    cudaGetSymbolAddress((void**)&tsq,  g_tsq);
    cudaGetSymbolAddress((void**)&tsk,  g_tsk);
    cudaGetSymbolAddress((void**)&qg,   g_qg);
    cudaGetSymbolAddress((void**)&kg,   g_kg);
    cudaGetSymbolAddress((void**)&scg,  g_scg);
    cudaGetSymbolAddress((void**)&adj,  g_adj);
    cudaGetSymbolAddress((void**)&hr,   g_hr);
    cudaGetSymbolAddress((void**)&feat, g_feat);
    cudaGetSymbolAddress((void**)&agg,  g_agg);
    cudaGetSymbolAddress((void**)&inp,  g_inp);
    cudaGetSymbolAddress((void**)&tq,   g_tq);
    cudaGetSymbolAddress((void**)&tk,   g_tk);
    cudaGetSymbolAddress((void**)&qp,   g_qp);
    cudaGetSymbolAddress((void**)&kp,   g_kp);
    cudaGetSymbolAddress((void**)&stg,  g_stg);
    cudaGetSymbolAddress((void**)&stp,  g_stp);
    cudaGetSymbolAddress((void**)&sp,   g_sp);

    const float inv = 0.125f;
    const long sd  = (long)Sx * DKx;
    const long ss  = (long)Sx * Sx;

    k_init_rope<<<48, 256>>>();

    // ---- graph threshold heads ----
    launch_gemm(x, 0, wq4gt_w, 0, wq4gt_b, lin, 0, Mx, 64, Hx, 0, 1.f, 1);
    k_rope<<<Mx, 32>>>(lin, amask, tsq, 1);
    launch_gemm(x, 0, wk4gt_w, 0, wk4gt_b, lin, 0, Mx, 64, Hx, 0, 1.f, 1);
    k_rope<<<Mx, 32>>>(lin, amask, tsk, 1);
    launch_gemm(tsq, sd, tsk, sd, nullptr, stg, ss, Sx, Sx, DKx, 0, inv, Bx);

    // ---- graph q/k (9 heads) ----
    launch_gemm(x, 0, wq4g_rep_w, 0, wq4g_rep_b, hid, 0, Mx, IGx, Hx, 1, 1.f, 1);
    launch_gemm(hid, 0, wq4g_sc_w, 0, wq4g_sc_b, lin, 0, Mx, 576, IGx, 0, 1.f, 1);
    k_rope<<<Mx, 288>>>(lin, amask, qg, 9);
    launch_gemm(x, 0, wk4g_rep_w, 0, wk4g_rep_b, hid, 0, Mx, IGx, Hx, 1, 1.f, 1);
    launch_gemm(hid, 0, wk4g_sc_w, 0, wk4g_sc_b, lin, 0, Mx, 576, IGx, 0, 1.f, 1);
    k_rope<<<Mx, 288>>>(lin, amask, kg, 9);
    launch_gemm(qg, sd, kg, sd, nullptr, scg, ss, Sx, Sx, DKx, 0, inv, Bx*HEADERx);
    k_adj<<<Bx*HEADERx*Sx, 128>>>(scg, adj);

    // ---- RGAT (2 layers) ----
    const float* f = x;
    for (int l = 0; l < 2; ++l) {
        launch_gemm(f, 0, rgat_w + (long)l*HEADERx*Hx*Hx, (long)Hx*Hx, nullptr,
                    hr, (long)Bx*Sx*Hx, Mx, Hx, Hx, 0, 1.f, HEADERx);
        k_mma_agg<<<dim3(Hx/64, Sx/128, Bx), 256>>>(adj, hr, agg);
        k_ln<<<Mx, 256>>>(agg, feat);
        f = feat;
    }

    // ---- concat ----
    k_concat<<<((long)Mx*H2x + 255)/256, 256>>>(x, feat, inp);

    // ---- prediction threshold heads ----
    launch_gemm(inp, 0, wq4t_w, 0, wq4t_b, lin, 0, Mx, 64, H2x, 0, 1.f, 1);
    k_rope<<<Mx, 32>>>(lin, amask, tq, 1);
    launch_gemm(inp, 0, wk4t_w, 0, wk4t_b, lin, 0, Mx, 64, H2x, 0, 1.f, 1);
    k_rope<<<Mx, 32>>>(lin, amask, tk, 1);
    launch_gemm(tq, sd, tk, sd, nullptr, stp, ss, Sx, Sx, DKx, 0, inv, Bx);

    // ---- prediction q/k (6 heads) ----
    launch_gemm(inp, 0, wq_rep_w, 0, wq_rep_b, hid, 0, Mx, IPx, H2x, 1, 1.f, 1);
    launch_gemm(hid, 0, wq_sc_w, 0, wq_sc_b, lin, 0, Mx, 384, IPx, 0, 1.f, 1);
    k_rope<<<Mx, 192>>>(lin, amask, qp, 6);
    launch_gemm(inp, 0, wk_rep_w, 0, wk_rep_b, hid, 0, Mx, IPx, H2x, 1, 1.f, 1);
    launch_gemm(hid, 0, wk_sc_w, 0, wk_sc_b, lin, 0, Mx, 384, IPx, 0, 1.f, 1);
    k_rope<<<Mx, 192>>>(lin, amask, kp, 6);
    launch_gemm(qp, sd, kp, sd, nullptr, sp, ss, Sx, Sx, DKx, 0, inv, Bx*ESSx);

    // ---- final gather ----
    k_pairs<<<dim3(Sx, Bx), Sx>>>(sp, stp, scg, stg, out);
}

// round 4
// speedup vs baseline: 1.5749x; 1.5749x over previous
#include <cuda_runtime.h>
#include <math.h>
#include <stdint.h>

#define Bx 16
#define Sx 384
#define Hx 768
#define ESSx 6
#define HEADERx 9
#define Px 73920
#define Mx (Bx*Sx)
#define SSx ((long)Sx*Sx)

// ---------------- fp32 scratch ----------------
__device__ float g_cos[Sx*32];
__device__ float g_sin[Sx*32];
__device__ __align__(16) float g_lin[Mx*576];
__device__ __align__(16) float g_scg[(size_t)Bx*HEADERx*Sx*Sx];
__device__ __align__(16) float g_stg[(size_t)Bx*Sx*Sx];
__device__ __align__(16) float g_stp[(size_t)Bx*Sx*Sx];
__device__ __align__(16) float g_sp [(size_t)Bx*ESSx*Sx*Sx];
__device__ __align__(16) float g_agg[Mx*Hx];

// ---------------- packed bf16 (hi,lo) k-pair scratch ----------------
__device__ __align__(16) uint32_t g_xh[Mx*384],   g_xl[Mx*384];
__device__ __align__(16) uint32_t g_hidh[Mx*480], g_hidl[Mx*480];
__device__ __align__(16) uint32_t g_tsqh[Mx*32],  g_tsql[Mx*32];
__device__ __align__(16) uint32_t g_tskh[Mx*32],  g_tskl[Mx*32];
__device__ __align__(16) uint32_t g_tqh[Mx*32],   g_tql[Mx*32];
__device__ __align__(16) uint32_t g_tkh[Mx*32],   g_tkl[Mx*32];
__device__ __align__(16) uint32_t g_qgh[Bx*HEADERx*Sx*32], g_qgl[Bx*HEADERx*Sx*32];
__device__ __align__(16) uint32_t g_kgh[Bx*HEADERx*Sx*32], g_kgl[Bx*HEADERx*Sx*32];
__device__ __align__(16) uint32_t g_qph[Bx*ESSx*Sx*32],    g_qpl[Bx*ESSx*Sx*32];
__device__ __align__(16) uint32_t g_kph[Bx*ESSx*Sx*32],    g_kpl[Bx*ESSx*Sx*32];
__device__ __align__(16) uint32_t g_adjh[(size_t)Bx*HEADERx*Sx*192], g_adjl[(size_t)Bx*HEADERx*Sx*192];
__device__ __align__(16) uint32_t g_hrh[(size_t)HEADERx*Hx*3072],    g_hrl[(size_t)HEADERx*Hx*3072];
__device__ __align__(16) uint32_t g_feath[Mx*384], g_featl[Mx*384];
__device__ __align__(16) uint32_t g_inph[Mx*768],  g_inpl[Mx*768];
// packed weights
__device__ __align__(16) uint32_t g_w1h[64*384],   g_w1l[64*384];
__device__ __align__(16) uint32_t g_w2h[64*384],   g_w2l[64*384];
__device__ __align__(16) uint32_t g_w3h[672*384],  g_w3l[672*384];
__device__ __align__(16) uint32_t g_w4h[672*384],  g_w4l[672*384];
__device__ __align__(16) uint32_t g_w5h[576*336],  g_w5l[576*336];
__device__ __align__(16) uint32_t g_w6h[576*336],  g_w6l[576*336];
__device__ __align__(16) uint32_t g_wrh[2*9*768*384], g_wrl[2*9*768*384];
__device__ __align__(16) uint32_t g_w7h[64*768],   g_w7l[64*768];
__device__ __align__(16) uint32_t g_w8h[64*768],   g_w8l[64*768];
__device__ __align__(16) uint32_t g_w9h[960*768],  g_w9l[960*768];
__device__ __align__(16) uint32_t g_w10h[960*768], g_w10l[960*768];
__device__ __align__(16) uint32_t g_w11h[384*480], g_w11l[384*480];
__device__ __align__(16) uint32_t g_w12h[384*480], g_w12l[384*480];

// ---------------- helpers ----------------
__device__ __forceinline__ uint32_t pack_bf(float x0, float x1) {
    uint32_t r;
    asm("cvt.rn.bf16x2.f32 %0, %1, %2;" : "=r"(r) : "f"(x1), "f"(x0));
    return r;
}
__device__ __forceinline__ void split2(float x0, float x1, uint32_t& h, uint32_t& l) {
    h = pack_bf(x0, x1);
    float h0 = __uint_as_float(h << 16);
    float h1 = __uint_as_float(h & 0xFFFF0000u);
    l = pack_bf(x0 - h0, x1 - h1);
}
__device__ __forceinline__ void mma_bf(float* d, const uint32_t* a, const uint32_t* b) {
    asm volatile(
        "mma.sync.aligned.m16n8k16.row.col.f32.bf16.bf16.f32 "
        "{%0,%1,%2,%3},{%4,%5,%6,%7},{%8,%9},{%0,%1,%2,%3};"
        : "+f"(d[0]), "+f"(d[1]), "+f"(d[2]), "+f"(d[3])
        : "r"(a[0]), "r"(a[1]), "r"(a[2]), "r"(a[3]), "r"(b[0]), "r"(b[1]));
}

__global__ void k_init_rope() {
    int idx = blockIdx.x * blockDim.x + threadIdx.x;
    if (idx >= Sx * 32) return;
    int p = idx / 32, i = idx & 31;
    double theta = (double)p * pow(10000.0, -(double)i / 32.0);
    g_cos[idx] = (float)cos(theta);
    g_sin[idx] = (float)sin(theta);
}

__global__ void k_split(const float* __restrict__ in, uint32_t* __restrict__ h,
                        uint32_t* __restrict__ l, long np)
{
    long p = (long)blockIdx.x * blockDim.x + threadIdx.x;
    if (p >= np) return;
    float2 v = ((const float2*)in)[p];
    uint32_t hh, ll;
    split2(v.x, v.y, hh, ll);
    h[p] = hh; l[p] = ll;
}

// ---------------- split-bf16 GEMM: C[z] = act( A[z] @ W[z]^T * scale + bias ) ----------------
// BM=BN=128, k-step 16 (8 pairs), 512 threads (16 warps 4x4), warp tile 32x32.
// flags: 1 = relu, 2 = packed output (pairs along N).
__global__ void __launch_bounds__(512) k_mma(
    const uint32_t* __restrict__ Ahg, const uint32_t* __restrict__ Alg, long astr,
    const uint32_t* __restrict__ Whg, const uint32_t* __restrict__ Wlg, long wstr,
    const float* __restrict__ bias,
    float* __restrict__ C, uint32_t* __restrict__ Ch, uint32_t* __restrict__ Cl, long cstr,
    int M, int N, int KP, int flags, float scale)
{
    __shared__ uint32_t SA[2][128][8];
    __shared__ uint32_t SB[2][128][8];

    int tid = threadIdx.x, lane = tid & 31;
    int g = lane >> 2, tg = lane & 3;
    int wid = tid >> 5, wm = wid >> 2, wn = wid & 3;
    int row0 = blockIdx.y * 128, col0 = blockIdx.x * 128;

    int larr = tid >> 8;
    int lrow = (tid >> 1) & 127;
    int lq   = tid & 1;

    const uint32_t* Asrc = (larr ? Alg : Ahg) + blockIdx.z * astr
                         + (long)(row0 + lrow) * KP + 4 * lq;
    bool wok = (col0 + lrow) < N;
    const uint32_t* Wsrc = (larr ? Wlg : Whg) + blockIdx.z * wstr
                         + (long)(wok ? (col0 + lrow) : 0) * KP + 4 * lq;

    uint4* sa = (uint4*)&SA[larr][lrow][(4 * lq) ^ (lrow & 4)];
    uint4* sb = (uint4*)&SB[larr][lrow][(4 * lq) ^ (lrow & 4)];

    float acc[2][4][4] = {};
    uint4 z4 = make_uint4(0, 0, 0, 0);
    uint4 pa = *(const uint4*)Asrc;
    uint4 pb = wok ? *(const uint4*)Wsrc : z4;

    for (int kp0 = 0; kp0 < KP; kp0 += 8) {
        __syncthreads();
        *sa = pa; *sb = pb;
        __syncthreads();
        if (kp0 + 8 < KP) {
            pa = *(const uint4*)(Asrc + kp0 + 8);
            pb = wok ? *(const uint4*)(Wsrc + kp0 + 8) : z4;
        }
        uint32_t ah[2][4], al[2][4], bh[4][2], bl[4][2];
#pragma unroll
        for (int mt = 0; mt < 2; ++mt) {
            int r = wm * 32 + mt * 16 + g, sw = r & 4;
            ah[mt][0] = SA[0][r][tg ^ sw];        ah[mt][1] = SA[0][r + 8][tg ^ sw];
            ah[mt][2] = SA[0][r][(tg + 4) ^ sw];  ah[mt][3] = SA[0][r + 8][(tg + 4) ^ sw];
            al[mt][0] = SA[1][r][tg ^ sw];        al[mt][1] = SA[1][r + 8][tg ^ sw];
            al[mt][2] = SA[1][r][(tg + 4) ^ sw];  al[mt][3] = SA[1][r + 8][(tg + 4) ^ sw];
        }
#pragma unroll
        for (int nt = 0; nt < 4; ++nt) {
            int c = wn * 32 + nt * 8 + g, sw = c & 4;
            bh[nt][0] = SB[0][c][tg ^ sw];   bh[nt][1] = SB[0][c][(tg + 4) ^ sw];
            bl[nt][0] = SB[1][c][tg ^ sw];   bl[nt][1] = SB[1][c][(tg + 4) ^ sw];
        }
#pragma unroll
        for (int mt = 0; mt < 2; ++mt)
#pragma unroll
            for (int nt = 0; nt < 4; ++nt) {
                mma_bf(acc[mt][nt], al[mt], bh[nt]);
                mma_bf(acc[mt][nt], ah[mt], bl[nt]);
                mma_bf(acc[mt][nt], ah[mt], bh[nt]);
            }
    }

    bool relu = flags & 1, packed = flags & 2;
#pragma unroll
    for (int mt = 0; mt < 2; ++mt) {
        int r = row0 + wm * 32 + mt * 16 + g;
#pragma unroll
        for (int nt = 0; nt < 4; ++nt) {
            int c = col0 + wn * 32 + nt * 8 + 2 * tg;
            if (c < N) {
                float b0 = bias ? bias[c] : 0.f;
                float b1 = bias ? bias[c + 1] : 0.f;
                float v00 = acc[mt][nt][0] * scale + b0, v01 = acc[mt][nt][1] * scale + b1;
                float v10 = acc[mt][nt][2] * scale + b0, v11 = acc[mt][nt][3] * scale + b1;
                if (relu) {
                    v00 = fmaxf(v00, 0.f); v01 = fmaxf(v01, 0.f);
                    v10 = fmaxf(v10, 0.f); v11 = fmaxf(v11, 0.f);
                }
                if (packed) {
                    uint32_t hh, ll;
                    long o = blockIdx.z * cstr + (long)r * (N >> 1) + (c >> 1);
                    split2(v00, v01, hh, ll); Ch[o] = hh; Cl[o] = ll;
                    o = blockIdx.z * cstr + (long)(r + 8) * (N >> 1) + (c >> 1);
                    split2(v10, v11, hh, ll); Ch[o] = hh; Cl[o] = ll;
                } else {
                    float* Cz = C + blockIdx.z * cstr;
                    *(float2*)&Cz[(long)r * N + c] = make_float2(v00, v01);
                    *(float2*)&Cz[(long)(r + 8) * N + c] = make_float2(v10, v11);
                }
            }
        }
    }
}

// ---------------- fused RGAT agg: agg[b,s,o] = sum_r relu( adj[b,r] @ hrT[r]^T )  ----------------
// adj packed [b*9+r][s][192 pairs]; hrT packed [r][o=768 rows][b*192 + tpair].
// BM=128 (s), BN=64 (o), k-step 16, 256 threads (8 warps 4x2).
__global__ void __launch_bounds__(256) k_mma_agg(
    const uint32_t* __restrict__ adjh, const uint32_t* __restrict__ adjl,
    const uint32_t* __restrict__ hrh,  const uint32_t* __restrict__ hrl,
    float* __restrict__ out)
{
    __shared__ uint32_t SA[2][128][8];
    __shared__ uint32_t SB[2][64][8];

    int b = blockIdx.z, row0 = blockIdx.y * 128, col0 = blockIdx.x * 64;
    int tid = threadIdx.x, lane = tid & 31;
    int g = lane >> 2, tg = lane & 3;
    int wid = tid >> 5, wm = wid >> 1, wn = wid & 1;

    int larr = tid >> 7;              // A/B array select
    int lrow = tid & 127;             // A row
    int brow = tid & 63;              // B row
    int bq   = (tid >> 6) & 1;        // B quad

    float sum[2][4][4] = {};

    for (int rel = 0; rel < HEADERx; ++rel) {
        const uint32_t* asrc = (larr ? adjl : adjh)
            + ((long)(b * HEADERx + rel) * Sx + row0 + lrow) * 192;
        const uint32_t* bsrc = (larr ? hrl : hrh)
            + (long)(rel * Hx + col0 + brow) * 3072 + b * 192 + 4 * bq;

        float acc[2][4][4] = {};
        uint4 pa0 = *(const uint4*)asrc;
        uint4 pa1 = *(const uint4*)(asrc + 4);
        uint4 pb  = *(const uint4*)bsrc;

        for (int kp0 = 0; kp0 < 192; kp0 += 8) {
            __syncthreads();
            *(uint4*)&SA[larr][lrow][0 ^ (lrow & 4)] = pa0;
            *(uint4*)&SA[larr][lrow][4 ^ (lrow & 4)] = pa1;
            *(uint4*)&SB[larr][brow][(4 * bq) ^ (brow & 4)] = pb;
            __syncthreads();
            if (kp0 + 8 < 192) {
                pa0 = *(const uint4*)(asrc + kp0 + 8);
                pa1 = *(const uint4*)(asrc + kp0 + 12);
                pb  = *(const uint4*)(bsrc + kp0 + 8);
            }
            uint32_t ah[2][4], al[2][4], bh[4][2], bl[4][2];
#pragma unroll
            for (int mt = 0; mt < 2; ++mt) {
                int r = wm * 32 + mt * 16 + g, sw = r & 4;
                ah[mt][0] = SA[0][r][tg ^ sw];        ah[mt][1] = SA[0][r + 8][tg ^ sw];
                ah[mt][2] = SA[0][r][(tg + 4) ^ sw];  ah[mt][3] = SA[0][r + 8][(tg + 4) ^ sw];
                al[mt][0] = SA[1][r][tg ^ sw];        al[mt][1] = SA[1][r + 8][tg ^ sw];
                al[mt][2] = SA[1][r][(tg + 4) ^ sw];  al[mt][3] = SA[1][r + 8][(tg + 4) ^ sw];
            }
#pragma unroll
            for (int nt = 0; nt < 4; ++nt) {
                int c = wn * 32 + nt * 8 + g, sw = c & 4;
                bh[nt][0] = SB[0][c][tg ^ sw];   bh[nt][1] = SB[0][c][(tg + 4) ^ sw];
                bl[nt][0] = SB[1][c][tg ^ sw];   bl[nt][1] = SB[1][c][(tg + 4) ^ sw];
            }
#pragma unroll
            for (int mt = 0; mt < 2; ++mt)
#pragma unroll
                for (int nt = 0; nt < 4; ++nt) {
                    mma_bf(acc[mt][nt], al[mt], bh[nt]);
                    mma_bf(acc[mt][nt], ah[mt], bl[nt]);
                    mma_bf(acc[mt][nt], ah[mt], bh[nt]);
                }
        }
#pragma unroll
        for (int mt = 0; mt < 2; ++mt)
#pragma unroll
            for (int nt = 0; nt < 4; ++nt)
#pragma unroll
                for (int i = 0; i < 4; ++i)
                    sum[mt][nt][i] += fmaxf(acc[mt][nt][i], 0.f);
        __syncthreads();
    }

#pragma unroll
    for (int mt = 0; mt < 2; ++mt) {
        int s = row0 + wm * 32 + mt * 16 + g;
#pragma unroll
        for (int nt = 0; nt < 4; ++nt) {
            int o = col0 + wn * 32 + nt * 8 + 2 * tg;
            *(float2*)&out[((long)b * Sx + s) * Hx + o] = make_float2(sum[mt][nt][0], sum[mt][nt][1]);
            *(float2*)&out[((long)b * Sx + s + 8) * Hx + o] = make_float2(sum[mt][nt][2], sum[mt][nt][3]);
        }
    }
}

// ---------------- mask + RoPE + head split -> packed ----------------
__global__ void k_rope(const float* __restrict__ lin, const float* __restrict__ mask,
                       uint32_t* __restrict__ qh, uint32_t* __restrict__ ql, int nH)
{
    int bs = blockIdx.x;
    int b = bs / Sx, s = bs % Sx;
    float m = mask[bs];
    int t = threadIdx.x;
    int h = t >> 5, i = t & 31;
    float c = g_cos[s * 32 + i], sn = g_sin[s * 32 + i];
    const float* lp = lin + (long)bs * nH * 64 + h * 64 + 2 * i;
    float x0 = lp[0] * m, x1 = lp[1] * m;
    float y0 = x0 * c - x1 * sn;
    float y1 = x1 * c + x0 * sn;
    uint32_t hh, ll;
    split2(y0, y1, hh, ll);
    long o = ((long)(b * nH + h) * Sx + s) * 32 + i;
    qh[o] = hh; ql[o] = ll;
}

// ---------------- in-place symmetrize: scg[i][j] = scg[j][i] for j < i ----------------
__global__ void k_sym(float* __restrict__ scg)
{
    int tj = blockIdx.x, ti = blockIdx.y, z = blockIdx.z;
    if (ti < tj) return;
    __shared__ float s[32][33];
    float* m = scg + (long)z * SSx;
    int tx = threadIdx.x;
    for (int a = threadIdx.y; a < 32; a += 8)
        s[a][tx] = m[(long)(tj * 32 + a) * Sx + ti * 32 + tx];
    __syncthreads();
    for (int a = threadIdx.y; a < 32; a += 8) {
        int i = ti * 32 + a, j = tj * 32 + tx;
        if (ti > tj || tx < a)
            m[(long)i * Sx + j] = s[tx][a];
    }
}

// ---------------- softmax row -> packed adj ----------------
__global__ void k_adj(const float* __restrict__ scg,
                      uint32_t* __restrict__ adjh, uint32_t* __restrict__ adjl)
{
    int i = blockIdx.x % Sx;
    long bh = blockIdx.x / Sx;
    const float* row = scg + bh * SSx + (long)i * Sx;
    int t = threadIdx.x;            // 192
    int lane = t & 31, w = t >> 5;
    float2 v = *(const float2*)&row[2 * t];

    __shared__ float red[6], red2[6];
    float m = fmaxf(v.x, v.y);
#pragma unroll
    for (int o = 16; o > 0; o >>= 1) m = fmaxf(m, __shfl_xor_sync(0xffffffffu, m, o));
    if (lane == 0) red[w] = m;
    __syncthreads();
    m = fmaxf(fmaxf(fmaxf(red[0], red[1]), fmaxf(red[2], red[3])), fmaxf(red[4], red[5]));
    float e0 = expf(v.x - m), e1 = expf(v.y - m);
    float s = e0 + e1;
#pragma unroll
    for (int o = 16; o > 0; o >>= 1) s += __shfl_xor_sync(0xffffffffu, s, o);
    if (lane == 0) red2[w] = s;
    __syncthreads();
    s = red2[0] + red2[1] + red2[2] + red2[3] + red2[4] + red2[5];
    float is = 1.f / s;
    float a0 = (v.x != 0.f) ? e0 * is : 0.f;
    float a1 = (v.y != 0.f) ? e1 * is : 0.f;
    uint32_t hh, ll;
    split2(a0, a1, hh, ll);
    long o = (bh * Sx + i) * 192 + t;
    adjh[o] = hh; adjl[o] = ll;
}

// ---------------- feat = layernorm( relu(agg)/9 ) -> packed ----------------
__global__ void k_ln(const float* __restrict__ agg, uint32_t* __restrict__ fh,
                     uint32_t* __restrict__ fl)
{
    long row = blockIdx.x;
    int t = threadIdx.x;            // 384
    int lane = t & 31, w = t >> 5;
    float2 xv = *(const float2*)&agg[row * Hx + 2 * t];
    float v0 = fmaxf(xv.x, 0.f) * (1.f / 9.f);
    float v1 = fmaxf(xv.y, 0.f) * (1.f / 9.f);

    __shared__ float red[12], red2[12];
    float s = v0 + v1;
#pragma unroll
    for (int o = 16; o > 0; o >>= 1) s += __shfl_xor_sync(0xffffffffu, s, o);
    if (lane == 0) red[w] = s;
    __syncthreads();
    float tot = 0.f;
#pragma unroll
    for (int u = 0; u < 12; ++u) tot += red[u];
    float mean = tot * (1.f / 768.f);
    float d0 = v0 - mean, d1 = v1 - mean;
    float s2 = d0 * d0 + d1 * d1;
#pragma unroll
    for (int o = 16; o > 0; o >>= 1) s2 += __shfl_xor_sync(0xffffffffu, s2, o);
    if (lane == 0) red2[w] = s2;
    __syncthreads();
    float tv = 0.f;
#pragma unroll
    for (int u = 0; u < 12; ++u) tv += red2[u];
    float rr = rsqrtf(tv * (1.f / 768.f) + 1e-5f);
    uint32_t hh, ll;
    split2(d0 * rr, d1 * rr, hh, ll);
    fh[row * 384 + t] = hh; fl[row * 384 + t] = ll;
}

// ---------------- inp = concat(x, feat) packed ----------------
__global__ void k_concat(const uint32_t* __restrict__ xh, const uint32_t* __restrict__ xl,
                         const uint32_t* __restrict__ fh, const uint32_t* __restrict__ fl,
                         uint32_t* __restrict__ ih, uint32_t* __restrict__ il)
{
    long idx = (long)blockIdx.x * blockDim.x + threadIdx.x;
    if (idx >= (long)Mx * 768) return;
    long row = idx / 768;
    int c = (int)(idx % 768);
    long src = row * 384 + (c < 384 ? c : c - 384);
    ih[idx] = (c < 384) ? xh[src] : fh[src];
    il[idx] = (c < 384) ? xl[src] : fl[src];
}

// ---------------- gather upper-triangle pairs -> out[B,P,16] ----------------
__global__ void k_pairs(const float* __restrict__ sp, const float* __restrict__ stp,
                        const float* __restrict__ sg, const float* __restrict__ stg,
                        float* __restrict__ out)
{
    int i = blockIdx.x, b = blockIdx.y, j = threadIdx.x;
    if (j < i) return;
    long p  = (long)i * (2 * Sx - i + 1) / 2 + (j - i);
    long ss = SSx;
    long ij = (long)i * Sx + j;
    const float* spb = sp + (long)b * ESSx * ss + ij;
    const float* sgb = sg + (long)b * HEADERx * ss + ij;
    float4 o0, o1, o2, o3;
    o0.x = spb[0];    o0.y = spb[ss];   o0.z = spb[2*ss]; o0.w = spb[3*ss];
    o1.x = spb[4*ss]; o1.y = spb[5*ss];
    o1.z = fmaxf(stp[(long)b*ss + ij], 0.f);
    o1.w = sgb[0];
    o2.x = sgb[ss];   o2.y = sgb[2*ss]; o2.z = sgb[3*ss]; o2.w = sgb[4*ss];
    o3.x = sgb[5*ss]; o3.y = sgb[6*ss]; o3.z = sgb[7*ss];
    o3.w = fmaxf(stg[(long)b*ss + ij], 0.f);
    float4* op = (float4*)(out + ((long)b * Px + p) * 16);
    op[0] = o0; op[1] = o1; op[2] = o2; op[3] = o3;
}

// ---------------- host ----------------
#define SYM(p, s) cudaGetSymbolAddress((void**)&p, s)

static void gsplit(const float* src, uint32_t* h, uint32_t* l, long elems) {
    long np = elems / 2;
    k_split<<<(int)((np + 255) / 256), 256>>>(src, h, l, np);
}
static void gemm(const uint32_t* Ah, const uint32_t* Al, long astr,
                 const uint32_t* Wh, const uint32_t* Wl, long wstr,
                 const float* bias, float* C, uint32_t* Ch, uint32_t* Cl, long cstr,
                 int M, int N, int KP, int flags, float scale, int Z)
{
    dim3 grid((N + 127) / 128, M / 128, Z);
    k_mma<<<grid, 512>>>(Ah, Al, astr, Wh, Wl, wstr, bias, C, Ch, Cl, cstr,
                         M, N, KP, flags, scale);
}

extern "C" void kernel_launch(void* const* d_in, const int* in_sizes, int n_in,
                              void* d_out, int out_size)
{
    const float* x       = (const float*)d_in[0];
    const float* amask   = (const float*)d_in[1];
    const float* w1      = (const float*)d_in[2];   const float* b1 = (const float*)d_in[3];
    const float* w2      = (const float*)d_in[4];   const float* b2 = (const float*)d_in[5];
    const float* w3      = (const float*)d_in[6];   const float* b3 = (const float*)d_in[7];
    const float* w5      = (const float*)d_in[8];   const float* b5 = (const float*)d_in[9];
    const float* w4      = (const float*)d_in[10];  const float* b4 = (const float*)d_in[11];
    const float* w6      = (const float*)d_in[12];  const float* b6 = (const float*)d_in[13];
    const float* rgat_w  = (const float*)d_in[14];
    const float* w7      = (const float*)d_in[15];  const float* b7 = (const float*)d_in[16];
    const float* w8      = (const float*)d_in[17];  const float* b8 = (const float*)d_in[18];
    const float* w9      = (const float*)d_in[19];  const float* b9 = (const float*)d_in[20];
    const float* w11     = (const float*)d_in[21];  const float* b11 = (const float*)d_in[22];
    const float* w10     = (const float*)d_in[23];  const float* b10 = (const float*)d_in[24];
    const float* w12     = (const float*)d_in[25];  const float* b12 = (const float*)d_in[26];
    float* out = (float*)d_out;

    float *lin, *scg, *stg, *stp, *sp, *agg;
    SYM(lin, g_lin); SYM(scg, g_scg); SYM(stg, g_stg); SYM(stp, g_stp);
    SYM(sp, g_sp);   SYM(agg, g_agg);
    uint32_t *xh,*xl,*hidh,*hidl,*tsqh,*tsql,*tskh,*tskl,*tqh,*tql,*tkh,*tkl;
    uint32_t *qgh,*qgl,*kgh,*kgl,*qph,*qpl,*kph,*kpl,*adjh,*adjl,*hrh,*hrl;
    uint32_t *feath,*featl,*inph,*inpl;
    uint32_t *w1h,*w1l,*w2h,*w2l,*w3h,*w3l,*w4h,*w4l,*w5h,*w5l,*w6h,*w6l;
    uint32_t *wrh,*wrl,*w7h,*w7l,*w8h,*w8l,*w9h,*w9l,*w10h,*w10l,*w11h,*w11l,*w12h,*w12l;
    SYM(xh,g_xh); SYM(xl,g_xl); SYM(hidh,g_hidh); SYM(hidl,g_hidl);
    SYM(tsqh,g_tsqh); SYM(tsql,g_tsql); SYM(tskh,g_tskh); SYM(tskl,g_tskl);
    SYM(tqh,g_tqh); SYM(tql,g_tql); SYM(tkh,g_tkh); SYM(tkl,g_tkl);
    SYM(qgh,g_qgh); SYM(qgl,g_qgl); SYM(kgh,g_kgh); SYM(kgl,g_kgl);
    SYM(qph,g_qph); SYM(qpl,g_qpl); SYM(kph,g_kph); SYM(kpl,g_kpl);
    SYM(adjh,g_adjh); SYM(adjl,g_adjl); SYM(hrh,g_hrh); SYM(hrl,g_hrl);
    SYM(feath,g_feath); SYM(featl,g_featl); SYM(inph,g_inph); SYM(inpl,g_inpl);
    SYM(w1h,g_w1h); SYM(w1l,g_w1l); SYM(w2h,g_w2h); SYM(w2l,g_w2l);
    SYM(w3h,g_w3h); SYM(w3l,g_w3l); SYM(w4h,g_w4h); SYM(w4l,g_w4l);
    SYM(w5h,g_w5h); SYM(w5l,g_w5l); SYM(w6h,g_w6h); SYM(w6l,g_w6l);
    SYM(wrh,g_wrh); SYM(wrl,g_wrl);
    SYM(w7h,g_w7h); SYM(w7l,g_w7l); SYM(w8h,g_w8h); SYM(w8l,g_w8l);
    SYM(w9h,g_w9h); SYM(w9l,g_w9l); SYM(w10h,g_w10h); SYM(w10l,g_w10l);
    SYM(w11h,g_w11h); SYM(w11l,g_w11l); SYM(w12h,g_w12h); SYM(w12l,g_w12l);

    const float inv = 0.125f;
    const long qs = (long)Sx * 32;

    k_init_rope<<<48, 256>>>();

    // one-time splits
    gsplit(x, xh, xl, (long)Mx * 768);
    gsplit(w1, w1h, w1l, 64 * 768);   gsplit(w2, w2h, w2l, 64 * 768);
    gsplit(w3, w3h, w3l, 672 * 768);  gsplit(w4, w4h, w4l, 672 * 768);
    gsplit(w5, w5h, w5l, 576 * 672);  gsplit(w6, w6h, w6l, 576 * 672);
    gsplit(rgat_w, wrh, wrl, (long)2 * 9 * 768 * 768);
    gsplit(w7, w7h, w7l, 64 * 1536);  gsplit(w8, w8h, w8l, 64 * 1536);
    gsplit(w9, w9h, w9l, 960 * 1536); gsplit(w10, w10h, w10l, 960 * 1536);
    gsplit(w11, w11h, w11l, 384 * 960); gsplit(w12, w12h, w12l, 384 * 960);

    // ---- graph threshold heads ----
    gemm(xh, xl, 0, w1h, w1l, 0, b1, lin, 0, 0, 0, Mx, 64, 384, 0, 1.f, 1);
    k_rope<<<Mx, 32>>>(lin, amask, tsqh, tsql, 1);
    gemm(xh, xl, 0, w2h, w2l, 0, b2, lin, 0, 0, 0, Mx, 64, 384, 0, 1.f, 1);
    k_rope<<<Mx, 32>>>(lin, amask, tskh, tskl, 1);
    gemm(tsqh, tsql, qs, tskh, tskl, qs, 0, stg, 0, 0, SSx, Sx, Sx, 32, 0, inv, Bx);

    // ---- graph q/k (9 heads) ----
    gemm(xh, xl, 0, w3h, w3l, 0, b3, 0, hidh, hidl, 0, Mx, 672, 384, 3, 1.f, 1);
    gemm(hidh, hidl, 0, w5h, w5l, 0, b5, lin, 0, 0, 0, Mx, 576, 336, 0, 1.f, 1);
    k_rope<<<Mx, 288>>>(lin, amask, qgh, qgl, 9);
    gemm(xh, xl, 0, w4h, w4l, 0, b4, 0, hidh, hidl, 0, Mx, 672, 384, 3, 1.f, 1);
    gemm(hidh, hidl, 0, w6h, w6l, 0, b6, lin, 0, 0, 0, Mx, 576, 336, 0, 1.f, 1);
    k_rope<<<Mx, 288>>>(lin, amask, kgh, kgl, 9);
    gemm(qgh, qgl, qs, kgh, kgl, qs, 0, scg, 0, 0, SSx, Sx, Sx, 32, 0, inv, Bx * HEADERx);
    k_sym<<<dim3(12, 12, Bx * HEADERx), dim3(32, 8)>>>(scg);
    k_adj<<<Bx * HEADERx * Sx, 192>>>(scg, adjh, adjl);

    // ---- RGAT (2 layers): hrT[r][o][t] = rgat_w[l][r] @ feat^T, packed along t ----
    const uint32_t* fth = xh; const uint32_t* ftl = xl;
    for (int l = 0; l < 2; ++l) {
        gemm(wrh + (long)l * 9 * 768 * 384, wrl + (long)l * 9 * 768 * 384, (long)768 * 384,
             fth, ftl, 0, 0, 0, hrh, hrl, (long)Hx * 3072, Hx, Mx, 384, 2, 1.f, HEADERx);
        k_mma_agg<<<dim3(12, 3, Bx), 256>>>(adjh, adjl, hrh, hrl, agg);
        k_ln<<<Mx, 384>>>(agg, feath, featl);
        fth = feath; ftl = featl;
    }

    // ---- concat ----
    k_concat<<<(int)(((long)Mx * 768 + 255) / 256), 256>>>(xh, xl, feath, featl, inph, inpl);

    // ---- prediction threshold heads ----
    gemm(inph, inpl, 0, w7h, w7l, 0, b7, lin, 0, 0, 0, Mx, 64, 768, 0, 1.f, 1);
    k_rope<<<Mx, 32>>>(lin, amask, tqh, tql, 1);
    gemm(inph, inpl, 0, w8h, w8l, 0, b8, lin, 0, 0, 0, Mx, 64, 768, 0, 1.f, 1);
    k_rope<<<Mx, 32>>>(lin, amask, tkh, tkl, 1);
    gemm(tqh, tql, qs, tkh, tkl, qs, 0, stp, 0, 0, SSx, Sx, Sx, 32, 0, inv, Bx);

    // ---- prediction q/k (6 heads) ----
    gemm(inph, inpl, 0, w9h, w9l, 0, b9, 0, hidh, hidl, 0, Mx, 960, 768, 3, 1.f, 1);
    gemm(hidh, hidl, 0, w11h, w11l, 0, b11, lin, 0, 0, 0, Mx, 384, 480, 0, 1.f, 1);
    k_rope<<<Mx, 192>>>(lin, amask, qph, qpl, 6);
    gemm(inph, inpl, 0, w10h, w10l, 0, b10, 0, hidh, hidl, 0, Mx, 960, 768, 3, 1.f, 1);
    gemm(hidh, hidl, 0, w12h, w12l, 0, b12, lin, 0, 0, 0, Mx, 384, 480, 0, 1.f, 1);
    k_rope<<<Mx, 192>>>(lin, amask, kph, kpl, 6);
    gemm(qph, qpl, qs, kph, kpl, qs, 0, sp, 0, 0, SSx, Sx, Sx, 32, 0, inv, Bx * ESSx);

    // ---- final gather ----
    k_pairs<<<dim3(Sx, Bx), Sx>>>(sp, stp, scg, stg, out);
}

// round 5
// speedup vs baseline: 1.8821x; 1.1951x over previous
#include <cuda_runtime.h>
#include <math.h>
#include <stdint.h>

#define Bx 16
#define Sx 384
#define Hx 768
#define ESSx 6
#define HEADERx 9
#define Px 73920
#define Mx (Bx*Sx)
#define SSx ((long)Sx*Sx)

// ---------------- fp32 scratch ----------------
__device__ float g_cos[Sx*32];
__device__ float g_sin[Sx*32];
__device__ __align__(16) float g_lin[Mx*576];
__device__ __align__(16) float g_scg[(size_t)Bx*HEADERx*Sx*Sx];
__device__ __align__(16) float g_stg[(size_t)Bx*Sx*Sx];
__device__ __align__(16) float g_stp[(size_t)Bx*Sx*Sx];
__device__ __align__(16) float g_sp [(size_t)Bx*ESSx*Sx*Sx];
__device__ __align__(16) float g_agg[Mx*Hx];

// ---------------- packed bf16 (hi,lo) k-pair scratch ----------------
__device__ __align__(16) uint32_t g_xh[Mx*384],   g_xl[Mx*384];
__device__ __align__(16) uint32_t g_hidh[Mx*480], g_hidl[Mx*480];
__device__ __align__(16) uint32_t g_tsqh[Mx*32],  g_tsql[Mx*32];
__device__ __align__(16) uint32_t g_tskh[Mx*32],  g_tskl[Mx*32];
__device__ __align__(16) uint32_t g_tqh[Mx*32],   g_tql[Mx*32];
__device__ __align__(16) uint32_t g_tkh[Mx*32],   g_tkl[Mx*32];
__device__ __align__(16) uint32_t g_qgh[Bx*HEADERx*Sx*32], g_qgl[Bx*HEADERx*Sx*32];
__device__ __align__(16) uint32_t g_kgh[Bx*HEADERx*Sx*32], g_kgl[Bx*HEADERx*Sx*32];
__device__ __align__(16) uint32_t g_qph[Bx*ESSx*Sx*32],    g_qpl[Bx*ESSx*Sx*32];
__device__ __align__(16) uint32_t g_kph[Bx*ESSx*Sx*32],    g_kpl[Bx*ESSx*Sx*32];
__device__ __align__(16) uint32_t g_adjh[(size_t)Bx*HEADERx*Sx*192], g_adjl[(size_t)Bx*HEADERx*Sx*192];
__device__ __align__(16) uint32_t g_hrh[(size_t)HEADERx*Hx*3072],    g_hrl[(size_t)HEADERx*Hx*3072];
__device__ __align__(16) uint32_t g_feath[Mx*384], g_featl[Mx*384];
__device__ __align__(16) uint32_t g_inph[Mx*768],  g_inpl[Mx*768];
// packed weights
__device__ __align__(16) uint32_t g_w1h[64*384],   g_w1l[64*384];
__device__ __align__(16) uint32_t g_w2h[64*384],   g_w2l[64*384];
__device__ __align__(16) uint32_t g_w3h[672*384],  g_w3l[672*384];
__device__ __align__(16) uint32_t g_w4h[672*384],  g_w4l[672*384];
__device__ __align__(16) uint32_t g_w5h[576*336],  g_w5l[576*336];
__device__ __align__(16) uint32_t g_w6h[576*336],  g_w6l[576*336];
__device__ __align__(16) uint32_t g_wrh[2*9*768*384], g_wrl[2*9*768*384];
__device__ __align__(16) uint32_t g_w7h[64*768],   g_w7l[64*768];
__device__ __align__(16) uint32_t g_w8h[64*768],   g_w8l[64*768];
__device__ __align__(16) uint32_t g_w9h[960*768],  g_w9l[960*768];
__device__ __align__(16) uint32_t g_w10h[960*768], g_w10l[960*768];
__device__ __align__(16) uint32_t g_w11h[384*480], g_w11l[384*480];
__device__ __align__(16) uint32_t g_w12h[384*480], g_w12l[384*480];

// ---------------- helpers ----------------
__device__ __forceinline__ uint32_t pack_bf(float x0, float x1) {
    uint32_t r;
    asm("cvt.rn.bf16x2.f32 %0, %1, %2;" : "=r"(r) : "f"(x1), "f"(x0));
    return r;
}
__device__ __forceinline__ void split2(float x0, float x1, uint32_t& h, uint32_t& l) {
    h = pack_bf(x0, x1);
    float h0 = __uint_as_float(h << 16);
    float h1 = __uint_as_float(h & 0xFFFF0000u);
    l = pack_bf(x0 - h0, x1 - h1);
}
__device__ __forceinline__ void mma_bf(float* d, const uint32_t* a, const uint32_t* b) {
    asm volatile(
        "mma.sync.aligned.m16n8k16.row.col.f32.bf16.bf16.f32 "
        "{%0,%1,%2,%3},{%4,%5,%6,%7},{%8,%9},{%0,%1,%2,%3};"
        : "+f"(d[0]), "+f"(d[1]), "+f"(d[2]), "+f"(d[3])
        : "r"(a[0]), "r"(a[1]), "r"(a[2]), "r"(a[3]), "r"(b[0]), "r"(b[1]));
}
__device__ __forceinline__ void ldsm4(uint32_t* r, uint32_t a) {
    asm volatile("ldmatrix.sync.aligned.m8n8.x4.shared.b16 {%0,%1,%2,%3},[%4];"
        : "=r"(r[0]), "=r"(r[1]), "=r"(r[2]), "=r"(r[3]) : "r"(a));
}

__global__ void k_init_rope() {
    int idx = blockIdx.x * blockDim.x + threadIdx.x;
    if (idx >= Sx * 32) return;
    int p = idx / 32, i = idx & 31;
    double theta = (double)p * pow(10000.0, -(double)i / 32.0);
    g_cos[idx] = (float)cos(theta);
    g_sin[idx] = (float)sin(theta);
}

__global__ void k_split(const float* __restrict__ in, uint32_t* __restrict__ h,
                        uint32_t* __restrict__ l, long np)
{
    long p = (long)blockIdx.x * blockDim.x + threadIdx.x;
    if (p >= np) return;
    float2 v = ((const float2*)in)[p];
    uint32_t hh, ll;
    split2(v.x, v.y, hh, ll);
    h[p] = hh; l[p] = ll;
}

// ---------------- split-bf16 GEMM (double-buffered + ldmatrix) ----------------
// C[z] = act( A[z] @ W[z]^T * scale + bias ); BM=BN=128, stage k=16 (8 pairs),
// 512 threads (16 warps 4x4), warp tile 32x32. flags: 1=relu, 2=packed output.
__global__ void __launch_bounds__(512) k_mma(
    const uint32_t* __restrict__ Ahg, const uint32_t* __restrict__ Alg, long astr,
    const uint32_t* __restrict__ Whg, const uint32_t* __restrict__ Wlg, long wstr,
    const float* __restrict__ bias,
    float* __restrict__ C, uint32_t* __restrict__ Ch, uint32_t* __restrict__ Cl, long cstr,
    int M, int N, int KP, int flags, float scale)
{
    __shared__ uint32_t SA[2][2][128][8];   // [stage][arr][row][pair]
    __shared__ uint32_t SB[2][2][128][8];

    int tid = threadIdx.x, lane = tid & 31;
    int g = lane >> 2, tg = lane & 3;
    int wid = tid >> 5, wm = wid >> 2, wn = wid & 3;
    int row0 = blockIdx.y * 128, col0 = blockIdx.x * 128;

    int larr = tid >> 8;
    int lrow = (tid >> 1) & 127;
    int lq   = tid & 1;

    const uint32_t* Asrc = (larr ? Alg : Ahg) + blockIdx.z * astr
                         + (long)(row0 + lrow) * KP + 4 * lq;
    bool wok = (col0 + lrow) < N;
    const uint32_t* Wsrc = (larr ? Wlg : Whg) + blockIdx.z * wstr
                         + (long)(wok ? (col0 + lrow) : 0) * KP + 4 * lq;

    uint32_t* saST = &SA[0][larr][lrow][(4 * lq) ^ (lrow & 4)];
    uint32_t* sbST = &SB[0][larr][lrow][(4 * lq) ^ (lrow & 4)];
    const int STW = 2 * 128 * 8;          // words per stage

    // ldmatrix lane addresses (stage 0, arr 0, tile 0 base)
    int lm = lane >> 3, ri = lane & 7;
    int arow = wm * 32 + (lm & 1) * 8 + ri;
    uint32_t aoff = ((arow * 8) + ((4 * (lm >> 1)) ^ (arow & 4))) * 4;
    int brow = wn * 32 + (lm >> 1) * 8 + ri;
    uint32_t boff = ((brow * 8) + ((4 * (lm & 1)) ^ (brow & 4))) * 4;
    uint32_t saBase = (uint32_t)__cvta_generic_to_shared(SA);
    uint32_t sbBase = (uint32_t)__cvta_generic_to_shared(SB);

    float acc[2][4][4] = {};
    uint4 z4 = make_uint4(0, 0, 0, 0);
    uint4 pa = *(const uint4*)Asrc;
    uint4 pb = wok ? *(const uint4*)Wsrc : z4;
    *(uint4*)saST = pa;
    *(uint4*)sbST = pb;
    __syncthreads();

    int stages = KP >> 3;
    for (int t = 0; t < stages; ++t) {
        int cur = t & 1;
        if (t + 1 < stages) {
            pa = *(const uint4*)(Asrc + (t + 1) * 8);
            pb = wok ? *(const uint4*)(Wsrc + (t + 1) * 8) : z4;
        }
        uint32_t ah[2][4], al[2][4], bH[2][4], bL[2][4];
        uint32_t sa0 = saBase + cur * (STW * 4) + aoff;
        uint32_t sb0 = sbBase + cur * (STW * 4) + boff;
#pragma unroll
        for (int mt = 0; mt < 2; ++mt) {
            ldsm4(ah[mt], sa0 + mt * 512);
            ldsm4(al[mt], sa0 + 4096 + mt * 512);
        }
#pragma unroll
        for (int np = 0; np < 2; ++np) {
            ldsm4(bH[np], sb0 + np * 512);
            ldsm4(bL[np], sb0 + 4096 + np * 512);
        }
#pragma unroll
        for (int mt = 0; mt < 2; ++mt)
#pragma unroll
            for (int nt = 0; nt < 4; ++nt) {
                const uint32_t* bh = &bH[nt >> 1][(nt & 1) * 2];
                const uint32_t* bl = &bL[nt >> 1][(nt & 1) * 2];
                mma_bf(acc[mt][nt], al[mt], bh);
                mma_bf(acc[mt][nt], ah[mt], bl);
                mma_bf(acc[mt][nt], ah[mt], bh);
            }
        if (t + 1 < stages) {
            *(uint4*)(saST + (cur ^ 1) * STW) = pa;
            *(uint4*)(sbST + (cur ^ 1) * STW) = pb;
        }
        __syncthreads();
    }

    bool relu = flags & 1, packed = flags & 2;
#pragma unroll
    for (int mt = 0; mt < 2; ++mt) {
        int r = row0 + wm * 32 + mt * 16 + g;
#pragma unroll
        for (int nt = 0; nt < 4; ++nt) {
            int c = col0 + wn * 32 + nt * 8 + 2 * tg;
            if (c < N) {
                float b0 = bias ? bias[c] : 0.f;
                float b1 = bias ? bias[c + 1] : 0.f;
                float v00 = acc[mt][nt][0] * scale + b0, v01 = acc[mt][nt][1] * scale + b1;
                float v10 = acc[mt][nt][2] * scale + b0, v11 = acc[mt][nt][3] * scale + b1;
                if (relu) {
                    v00 = fmaxf(v00, 0.f); v01 = fmaxf(v01, 0.f);
                    v10 = fmaxf(v10, 0.f); v11 = fmaxf(v11, 0.f);
                }
                if (packed) {
                    uint32_t hh, ll;
                    long o = blockIdx.z * cstr + (long)r * (N >> 1) + (c >> 1);
                    split2(v00, v01, hh, ll); Ch[o] = hh; Cl[o] = ll;
                    o = blockIdx.z * cstr + (long)(r + 8) * (N >> 1) + (c >> 1);
                    split2(v10, v11, hh, ll); Ch[o] = hh; Cl[o] = ll;
                } else {
                    float* Cz = C + blockIdx.z * cstr;
                    *(float2*)&Cz[(long)r * N + c] = make_float2(v00, v01);
                    *(float2*)&Cz[(long)(r + 8) * N + c] = make_float2(v10, v11);
                }
            }
        }
    }
}

// ---------------- fused RGAT agg (double-buffered + ldmatrix) ----------------
// agg[b,s,o] = sum_r relu( adj[b,r] @ hrT[r]^T ); BM=128, BN=64, 256 threads (8 warps 4x2).
__global__ void __launch_bounds__(256) k_mma_agg(
    const uint32_t* __restrict__ adjh, const uint32_t* __restrict__ adjl,
    const uint32_t* __restrict__ hrh,  const uint32_t* __restrict__ hrl,
    float* __restrict__ out)
{
    __shared__ uint32_t SA[2][2][128][8];
    __shared__ uint32_t SB[2][2][64][8];

    int b = blockIdx.z, row0 = blockIdx.y * 128, col0 = blockIdx.x * 64;
    int tid = threadIdx.x, lane = tid & 31;
    int g = lane >> 2, tg = lane & 3;
    int wid = tid >> 5, wm = wid >> 1, wn = wid & 1;

    int larr = tid >> 7;
    int lrow = tid & 127;
    int brw  = tid & 63;
    int bq   = (tid >> 6) & 1;

    uint32_t* saST0 = &SA[0][larr][lrow][0 ^ (lrow & 4)];
    uint32_t* saST1 = &SA[0][larr][lrow][4 ^ (lrow & 4)];
    uint32_t* sbST  = &SB[0][larr][brw][(4 * bq) ^ (brw & 4)];
    const int STWA = 2 * 128 * 8, STWB = 2 * 64 * 8;

    int lm = lane >> 3, ri = lane & 7;
    int arow = wm * 32 + (lm & 1) * 8 + ri;
    uint32_t aoff = ((arow * 8) + ((4 * (lm >> 1)) ^ (arow & 4))) * 4;
    int brow = wn * 32 + (lm >> 1) * 8 + ri;
    uint32_t boff = ((brow * 8) + ((4 * (lm & 1)) ^ (brow & 4))) * 4;
    uint32_t saBase = (uint32_t)__cvta_generic_to_shared(SA);
    uint32_t sbBase = (uint32_t)__cvta_generic_to_shared(SB);

    float sum[2][4][4] = {};

    for (int rel = 0; rel < HEADERx; ++rel) {
        const uint32_t* asrc = (larr ? adjl : adjh)
            + ((long)(b * HEADERx + rel) * Sx + row0 + lrow) * 192;
        const uint32_t* bsrc = (larr ? hrl : hrh)
            + (long)(rel * Hx + col0 + brw) * 3072 + b * 192 + 4 * bq;

        float acc[2][4][4] = {};
        uint4 pa0 = *(const uint4*)asrc;
        uint4 pa1 = *(const uint4*)(asrc + 4);
        uint4 pb  = *(const uint4*)bsrc;
        *(uint4*)saST0 = pa0;
        *(uint4*)saST1 = pa1;
        *(uint4*)sbST  = pb;
        __syncthreads();

        for (int t = 0; t < 24; ++t) {       // 192 pairs / 8
            int cur = t & 1;
            if (t + 1 < 24) {
                pa0 = *(const uint4*)(asrc + (t + 1) * 8);
                pa1 = *(const uint4*)(asrc + (t + 1) * 8 + 4);
                pb  = *(const uint4*)(bsrc + (t + 1) * 8);
            }
            uint32_t ah[2][4], al[2][4], bH[2][4], bL[2][4];
            uint32_t sa0 = saBase + cur * (STWA * 4) + aoff;
            uint32_t sb0 = sbBase + cur * (STWB * 4) + boff;
#pragma unroll
            for (int mt = 0; mt < 2; ++mt) {
                ldsm4(ah[mt], sa0 + mt * 512);
                ldsm4(al[mt], sa0 + 4096 + mt * 512);
            }
#pragma unroll
            for (int np = 0; np < 2; ++np) {
                ldsm4(bH[np], sb0 + np * 512);
                ldsm4(bL[np], sb0 + 2048 + np * 512);
            }
#pragma unroll
            for (int mt = 0; mt < 2; ++mt)
#pragma unroll
                for (int nt = 0; nt < 4; ++nt) {
                    const uint32_t* bh = &bH[nt >> 1][(nt & 1) * 2];
                    const uint32_t* bl = &bL[nt >> 1][(nt & 1) * 2];
                    mma_bf(acc[mt][nt], al[mt], bh);
                    mma_bf(acc[mt][nt], ah[mt], bl);
                    mma_bf(acc[mt][nt], ah[mt], bh);
                }
            if (t + 1 < 24) {
                *(uint4*)(saST0 + (cur ^ 1) * STWA) = pa0;
                *(uint4*)(saST1 + (cur ^ 1) * STWA) = pa1;
                *(uint4*)(sbST  + (cur ^ 1) * STWB) = pb;
            }
            __syncthreads();
        }
#pragma unroll
        for (int mt = 0; mt < 2; ++mt)
#pragma unroll
            for (int nt = 0; nt < 4; ++nt)
#pragma unroll
                for (int i = 0; i < 4; ++i)
                    sum[mt][nt][i] += fmaxf(acc[mt][nt][i], 0.f);
    }

#pragma unroll
    for (int mt = 0; mt < 2; ++mt) {
        int s = row0 + wm * 32 + mt * 16 + g;
#pragma unroll
        for (int nt = 0; nt < 4; ++nt) {
            int o = col0 + wn * 32 + nt * 8 + 2 * tg;
            *(float2*)&out[((long)b * Sx + s) * Hx + o] = make_float2(sum[mt][nt][0], sum[mt][nt][1]);
            *(float2*)&out[((long)b * Sx + s + 8) * Hx + o] = make_float2(sum[mt][nt][2], sum[mt][nt][3]);
        }
    }
}

// ---------------- mask + RoPE + head split -> packed ----------------
__global__ void k_rope(const float* __restrict__ lin, const float* __restrict__ mask,
                       uint32_t* __restrict__ qh, uint32_t* __restrict__ ql, int nH)
{
    int bs = blockIdx.x;
    int b = bs / Sx, s = bs % Sx;
    float m = mask[bs];
    int t = threadIdx.x;
    int h = t >> 5, i = t & 31;
    float c = g_cos[s * 32 + i], sn = g_sin[s * 32 + i];
    const float* lp = lin + (long)bs * nH * 64 + h * 64 + 2 * i;
    float x0 = lp[0] * m, x1 = lp[1] * m;
    float y0 = x0 * c - x1 * sn;
    float y1 = x1 * c + x0 * sn;
    uint32_t hh, ll;
    split2(y0, y1, hh, ll);
    long o = ((long)(b * nH + h) * Sx + s) * 32 + i;
    qh[o] = hh; ql[o] = ll;
}

// ---------------- in-place symmetrize ----------------
__global__ void k_sym(float* __restrict__ scg)
{
    int tj = blockIdx.x, ti = blockIdx.y, z = blockIdx.z;
    if (ti < tj) return;
    __shared__ float s[32][33];
    float* m = scg + (long)z * SSx;
    int tx = threadIdx.x;
    for (int a = threadIdx.y; a < 32; a += 8)
        s[a][tx] = m[(long)(tj * 32 + a) * Sx + ti * 32 + tx];
    __syncthreads();
    for (int a = threadIdx.y; a < 32; a += 8) {
        int i = ti * 32 + a, j = tj * 32 + tx;
        if (ti > tj || tx < a)
            m[(long)i * Sx + j] = s[tx][a];
    }
}

// ---------------- softmax row -> packed adj ----------------
__global__ void k_adj(const float* __restrict__ scg,
                      uint32_t* __restrict__ adjh, uint32_t* __restrict__ adjl)
{
    int i = blockIdx.x % Sx;
    long bh = blockIdx.x / Sx;
    const float* row = scg + bh * SSx + (long)i * Sx;
    int t = threadIdx.x;            // 192
    int lane = t & 31, w = t >> 5;
    float2 v = *(const float2*)&row[2 * t];

    __shared__ float red[6], red2[6];
    float m = fmaxf(v.x, v.y);
#pragma unroll
    for (int o = 16; o > 0; o >>= 1) m = fmaxf(m, __shfl_xor_sync(0xffffffffu, m, o));
    if (lane == 0) red[w] = m;
    __syncthreads();
    m = fmaxf(fmaxf(fmaxf(red[0], red[1]), fmaxf(red[2], red[3])), fmaxf(red[4], red[5]));
    float e0 = expf(v.x - m), e1 = expf(v.y - m);
    float s = e0 + e1;
#pragma unroll
    for (int o = 16; o > 0; o >>= 1) s += __shfl_xor_sync(0xffffffffu, s, o);
    if (lane == 0) red2[w] = s;
    __syncthreads();
    s = red2[0] + red2[1] + red2[2] + red2[3] + red2[4] + red2[5];
    float is = 1.f / s;
    float a0 = (v.x != 0.f) ? e0 * is : 0.f;
    float a1 = (v.y != 0.f) ? e1 * is : 0.f;
    uint32_t hh, ll;
    split2(a0, a1, hh, ll);
    long o = (bh * Sx + i) * 192 + t;
    adjh[o] = hh; adjl[o] = ll;
}

// ---------------- feat = layernorm( relu(agg)/9 ) -> packed ----------------
__global__ void k_ln(const float* __restrict__ agg, uint32_t* __restrict__ fh,
                     uint32_t* __restrict__ fl)
{
    long row = blockIdx.x;
    int t = threadIdx.x;            // 384
    int lane = t & 31, w = t >> 5;
    float2 xv = *(const float2*)&agg[row * Hx + 2 * t];
    float v0 = fmaxf(xv.x, 0.f) * (1.f / 9.f);
    float v1 = fmaxf(xv.y, 0.f) * (1.f / 9.f);

    __shared__ float red[12], red2[12];
    float s = v0 + v1;
#pragma unroll
    for (int o = 16; o > 0; o >>= 1) s += __shfl_xor_sync(0xffffffffu, s, o);
    if (lane == 0) red[w] = s;
    __syncthreads();
    float tot = 0.f;
#pragma unroll
    for (int u = 0; u < 12; ++u) tot += red[u];
    float mean = tot * (1.f / 768.f);
    float d0 = v0 - mean, d1 = v1 - mean;
    float s2 = d0 * d0 + d1 * d1;
#pragma unroll
    for (int o = 16; o > 0; o >>= 1) s2 += __shfl_xor_sync(0xffffffffu, s2, o);
    if (lane == 0) red2[w] = s2;
    __syncthreads();
    float tv = 0.f;
#pragma unroll
    for (int u = 0; u < 12; ++u) tv += red2[u];
    float rr = rsqrtf(tv * (1.f / 768.f) + 1e-5f);
    uint32_t hh, ll;
    split2(d0 * rr, d1 * rr, hh, ll);
    fh[row * 384 + t] = hh; fl[row * 384 + t] = ll;
}

// ---------------- inp = concat(x, feat) packed ----------------
__global__ void k_concat(const uint32_t* __restrict__ xh, const uint32_t* __restrict__ xl,
                         const uint32_t* __restrict__ fh, const uint32_t* __restrict__ fl,
                         uint32_t* __restrict__ ih, uint32_t* __restrict__ il)
{
    long idx = (long)blockIdx.x * blockDim.x + threadIdx.x;
    if (idx >= (long)Mx * 768) return;
    long row = idx / 768;
    int c = (int)(idx % 768);
    long src = row * 384 + (c < 384 ? c : c - 384);
    ih[idx] = (c < 384) ? xh[src] : fh[src];
    il[idx] = (c < 384) ? xl[src] : fl[src];
}

// ---------------- gather upper-triangle pairs -> out[B,P,16] ----------------
__global__ void k_pairs(const float* __restrict__ sp, const float* __restrict__ stp,
                        const float* __restrict__ sg, const float* __restrict__ stg,
                        float* __restrict__ out)
{
    int i = blockIdx.x, b = blockIdx.y, j = threadIdx.x;
    if (j < i) return;
    long p  = (long)i * (2 * Sx - i + 1) / 2 + (j - i);
    long ss = SSx;
    long ij = (long)i * Sx + j;
    const float* spb = sp + (long)b * ESSx * ss + ij;
    const float* sgb = sg + (long)b * HEADERx * ss + ij;
    float4 o0, o1, o2, o3;
    o0.x = spb[0];    o0.y = spb[ss];   o0.z = spb[2*ss]; o0.w = spb[3*ss];
    o1.x = spb[4*ss]; o1.y = spb[5*ss];
    o1.z = fmaxf(stp[(long)b*ss + ij], 0.f);
    o1.w = sgb[0];
    o2.x = sgb[ss];   o2.y = sgb[2*ss]; o2.z = sgb[3*ss]; o2.w = sgb[4*ss];
    o3.x = sgb[5*ss]; o3.y = sgb[6*ss]; o3.z = sgb[7*ss];
    o3.w = fmaxf(stg[(long)b*ss + ij], 0.f);
    float4* op = (float4*)(out + ((long)b * Px + p) * 16);
    op[0] = o0; op[1] = o1; op[2] = o2; op[3] = o3;
}

// ---------------- host ----------------
#define SYM(p, s) cudaGetSymbolAddress((void**)&p, s)

static void gsplit(const float* src, uint32_t* h, uint32_t* l, long elems) {
    long np = elems / 2;
    k_split<<<(int)((np + 255) / 256), 256>>>(src, h, l, np);
}
static void gemm(const uint32_t* Ah, const uint32_t* Al, long astr,
                 const uint32_t* Wh, const uint32_t* Wl, long wstr,
                 const float* bias, float* C, uint32_t* Ch, uint32_t* Cl, long cstr,
                 int M, int N, int KP, int flags, float scale, int Z)
{
    dim3 grid((N + 127) / 128, M / 128, Z);
    k_mma<<<grid, 512>>>(Ah, Al, astr, Wh, Wl, wstr, bias, C, Ch, Cl, cstr,
                         M, N, KP, flags, scale);
}

extern "C" void kernel_launch(void* const* d_in, const int* in_sizes, int n_in,
                              void* d_out, int out_size)
{
    const float* x       = (const float*)d_in[0];
    const float* amask   = (const float*)d_in[1];
    const float* w1      = (const float*)d_in[2];   const float* b1 = (const float*)d_in[3];
    const float* w2      = (const float*)d_in[4];   const float* b2 = (const float*)d_in[5];
    const float* w3      = (const float*)d_in[6];   const float* b3 = (const float*)d_in[7];
    const float* w5      = (const float*)d_in[8];   const float* b5 = (const float*)d_in[9];
    const float* w4      = (const float*)d_in[10];  const float* b4 = (const float*)d_in[11];
    const float* w6      = (const float*)d_in[12];  const float* b6 = (const float*)d_in[13];
    const float* rgat_w  = (const float*)d_in[14];
    const float* w7      = (const float*)d_in[15];  const float* b7 = (const float*)d_in[16];
    const float* w8      = (const float*)d_in[17];  const float* b8 = (const float*)d_in[18];
    const float* w9      = (const float*)d_in[19];  const float* b9 = (const float*)d_in[20];
    const float* w11     = (const float*)d_in[21];  const float* b11 = (const float*)d_in[22];
    const float* w10     = (const float*)d_in[23];  const float* b10 = (const float*)d_in[24];
    const float* w12     = (const float*)d_in[25];  const float* b12 = (const float*)d_in[26];
    float* out = (float*)d_out;

    float *lin, *scg, *stg, *stp, *sp, *agg;
    SYM(lin, g_lin); SYM(scg, g_scg); SYM(stg, g_stg); SYM(stp, g_stp);
    SYM(sp, g_sp);   SYM(agg, g_agg);
    uint32_t *xh,*xl,*hidh,*hidl,*tsqh,*tsql,*tskh,*tskl,*tqh,*tql,*tkh,*tkl;
    uint32_t *qgh,*qgl,*kgh,*kgl,*qph,*qpl,*kph,*kpl,*adjh,*adjl,*hrh,*hrl;
    uint32_t *feath,*featl,*inph,*inpl;
    uint32_t *w1h,*w1l,*w2h,*w2l,*w3h,*w3l,*w4h,*w4l,*w5h,*w5l,*w6h,*w6l;
    uint32_t *wrh,*wrl,*w7h,*w7l,*w8h,*w8l,*w9h,*w9l,*w10h,*w10l,*w11h,*w11l,*w12h,*w12l;
    SYM(xh,g_xh); SYM(xl,g_xl); SYM(hidh,g_hidh); SYM(hidl,g_hidl);
    SYM(tsqh,g_tsqh); SYM(tsql,g_tsql); SYM(tskh,g_tskh); SYM(tskl,g_tskl);
    SYM(tqh,g_tqh); SYM(tql,g_tql); SYM(tkh,g_tkh); SYM(tkl,g_tkl);
    SYM(qgh,g_qgh); SYM(qgl,g_qgl); SYM(kgh,g_kgh); SYM(kgl,g_kgl);
    SYM(qph,g_qph); SYM(qpl,g_qpl); SYM(kph,g_kph); SYM(kpl,g_kpl);
    SYM(adjh,g_adjh); SYM(adjl,g_adjl); SYM(hrh,g_hrh); SYM(hrl,g_hrl);
    SYM(feath,g_feath); SYM(featl,g_featl); SYM(inph,g_inph); SYM(inpl,g_inpl);
    SYM(w1h,g_w1h); SYM(w1l,g_w1l); SYM(w2h,g_w2h); SYM(w2l,g_w2l);
    SYM(w3h,g_w3h); SYM(w3l,g_w3l); SYM(w4h,g_w4h); SYM(w4l,g_w4l);
    SYM(w5h,g_w5h); SYM(w5l,g_w5l); SYM(w6h,g_w6h); SYM(w6l,g_w6l);
    SYM(wrh,g_wrh); SYM(wrl,g_wrl);
    SYM(w7h,g_w7h); SYM(w7l,g_w7l); SYM(w8h,g_w8h); SYM(w8l,g_w8l);
    SYM(w9h,g_w9h); SYM(w9l,g_w9l); SYM(w10h,g_w10h); SYM(w10l,g_w10l);
    SYM(w11h,g_w11h); SYM(w11l,g_w11l); SYM(w12h,g_w12h); SYM(w12l,g_w12l);

    const float inv = 0.125f;
    const long qs = (long)Sx * 32;

    k_init_rope<<<48, 256>>>();

    // one-time splits
    gsplit(x, xh, xl, (long)Mx * 768);
    gsplit(w1, w1h, w1l, 64 * 768);   gsplit(w2, w2h, w2l, 64 * 768);
    gsplit(w3, w3h, w3l, 672 * 768);  gsplit(w4, w4h, w4l, 672 * 768);
    gsplit(w5, w5h, w5l, 576 * 672);  gsplit(w6, w6h, w6l, 576 * 672);
    gsplit(rgat_w, wrh, wrl, (long)2 * 9 * 768 * 768);
    gsplit(w7, w7h, w7l, 64 * 1536);  gsplit(w8, w8h, w8l, 64 * 1536);
    gsplit(w9, w9h, w9l, 960 * 1536); gsplit(w10, w10h, w10l, 960 * 1536);
    gsplit(w11, w11h, w11l, 384 * 960); gsplit(w12, w12h, w12l, 384 * 960);

    // ---- graph threshold heads ----
    gemm(xh, xl, 0, w1h, w1l, 0, b1, lin, 0, 0, 0, Mx, 64, 384, 0, 1.f, 1);
    k_rope<<<Mx, 32>>>(lin, amask, tsqh, tsql, 1);
    gemm(xh, xl, 0, w2h, w2l, 0, b2, lin, 0, 0, 0, Mx, 64, 384, 0, 1.f, 1);
    k_rope<<<Mx, 32>>>(lin, amask, tskh, tskl, 1);
    gemm(tsqh, tsql, qs, tskh, tskl, qs, 0, stg, 0, 0, SSx, Sx, Sx, 32, 0, inv, Bx);

    // ---- graph q/k (9 heads) ----
    gemm(xh, xl, 0, w3h, w3l, 0, b3, 0, hidh, hidl, 0, Mx, 672, 384, 3, 1.f, 1);
    gemm(hidh, hidl, 0, w5h, w5l, 0, b5, lin, 0, 0, 0, Mx, 576, 336, 0, 1.f, 1);
    k_rope<<<Mx, 288>>>(lin, amask, qgh, qgl, 9);
    gemm(xh, xl, 0, w4h, w4l, 0, b4, 0, hidh, hidl, 0, Mx, 672, 384, 3, 1.f, 1);
    gemm(hidh, hidl, 0, w6h, w6l, 0, b6, lin, 0, 0, 0, Mx, 576, 336, 0, 1.f, 1);
    k_rope<<<Mx, 288>>>(lin, amask, kgh, kgl, 9);
    gemm(qgh, qgl, qs, kgh, kgl, qs, 0, scg, 0, 0, SSx, Sx, Sx, 32, 0, inv, Bx * HEADERx);
    k_sym<<<dim3(12, 12, Bx * HEADERx), dim3(32, 8)>>>(scg);
    k_adj<<<Bx * HEADERx * Sx, 192>>>(scg, adjh, adjl);

    // ---- RGAT (2 layers) ----
    const uint32_t* fth = xh; const uint32_t* ftl = xl;
    for (int l = 0; l < 2; ++l) {
        gemm(wrh + (long)l * 9 * 768 * 384, wrl + (long)l * 9 * 768 * 384, (long)768 * 384,
             fth, ftl, 0, 0, 0, hrh, hrl, (long)Hx * 3072, Hx, Mx, 384, 2, 1.f, HEADERx);
        k_mma_agg<<<dim3(12, 3, Bx), 256>>>(adjh, adjl, hrh, hrl, agg);
        k_ln<<<Mx, 384>>>(agg, feath, featl);
        fth = feath; ftl = featl;
    }

    // ---- concat ----
    k_concat<<<(int)(((long)Mx * 768 + 255) / 256), 256>>>(xh, xl, feath, featl, inph, inpl);

    // ---- prediction threshold heads ----
    gemm(inph, inpl, 0, w7h, w7l, 0, b7, lin, 0, 0, 0, Mx, 64, 768, 0, 1.f, 1);
    k_rope<<<Mx, 32>>>(lin, amask, tqh, tql, 1);
    gemm(inph, inpl, 0, w8h, w8l, 0, b8, lin, 0, 0, 0, Mx, 64, 768, 0, 1.f, 1);
    k_rope<<<Mx, 32>>>(lin, amask, tkh, tkl, 1);
    gemm(tqh, tql, qs, tkh, tkl, qs, 0, stp, 0, 0, SSx, Sx, Sx, 32, 0, inv, Bx);

    // ---- prediction q/k (6 heads) ----
    gemm(inph, inpl, 0, w9h, w9l, 0, b9, 0, hidh, hidl, 0, Mx, 960, 768, 3, 1.f, 1);
    gemm(hidh, hidl, 0, w11h, w11l, 0, b11, lin, 0, 0, 0, Mx, 384, 480, 0, 1.f, 1);
    k_rope<<<Mx, 192>>>(lin, amask, qph, qpl, 6);
    gemm(inph, inpl, 0, w10h, w10l, 0, b10, 0, hidh, hidl, 0, Mx, 960, 768, 3, 1.f, 1);
    gemm(hidh, hidl, 0, w12h, w12l, 0, b12, lin, 0, 0, 0, Mx, 384, 480, 0, 1.f, 1);
    k_rope<<<Mx, 192>>>(lin, amask, kph, kpl, 6);
    gemm(qph, qpl, qs, kph, kpl, qs, 0, sp, 0, 0, SSx, Sx, Sx, 32, 0, inv, Bx * ESSx);

    // ---- final gather ----
    k_pairs<<<dim3(Sx, Bx), Sx>>>(sp, stp, scg, stg, out);
}